// round 1
// baseline (speedup 1.0000x reference)
#include <cuda_runtime.h>
#include <cuda_bf16.h>
#include <cstdint>

// Problem constants
#define BB 32
#define DD 64
#define TT 2048
#define KK 1024
#define NN (BB * TT)              // 65536 rows
#define QELEMS (BB * DD * TT)     // 4194304
// Output layout (float32): [loss(1) | quantized(QELEMS) | indices(NN) | n_resurrected(1)]

#define CHUNK_K 128               // codewords staged in smem per iteration (32 KB)
#define BLOCK_T 128               // threads per block, 1 row per thread
#define GRID_B  (NN / BLOCK_T)    // 512 blocks

__device__ float g_wnorm[KK * DD];     // normalized codebook
__device__ float g_partial[GRID_B];    // per-block squared-error partial sums

// ---------------------------------------------------------------------------
// Kernel A: L2-normalize codebook rows. One warp per row (2 elems / lane).
// ---------------------------------------------------------------------------
__global__ void norm_weight_kernel(const float* __restrict__ w) {
    int row  = blockIdx.x * blockDim.y + threadIdx.y;   // 0..1023
    int lane = threadIdx.x;                              // 0..31
    float a = w[row * DD + lane];
    float b = w[row * DD + 32 + lane];
    float s = a * a + b * b;
    #pragma unroll
    for (int o = 16; o; o >>= 1) s += __shfl_xor_sync(0xFFFFFFFFu, s, o);
    float inv = 1.0f / fmaxf(sqrtf(s), 1e-12f);
    g_wnorm[row * DD + lane]      = a * inv;
    g_wnorm[row * DD + 32 + lane] = b * inv;
}

// ---------------------------------------------------------------------------
// Kernel B: per-row normalize + argmax dot over K codewords + gather/scatter.
// One thread per row. Codebook streamed through smem in CHUNK_K slabs; all
// lanes read the same smem word each step -> broadcast, conflict-free.
// ---------------------------------------------------------------------------
__global__ __launch_bounds__(BLOCK_T)
void vq_main_kernel(const float* __restrict__ in, float* __restrict__ out) {
    __shared__ float sw[CHUNK_K * DD];    // 32 KB
    __shared__ float red[BLOCK_T];

    int n = blockIdx.x * BLOCK_T + threadIdx.x;   // row id
    int b = n >> 11;                               // n / T  (T = 2048)
    int t = n & (TT - 1);                          // n % T

    // Load row x (strided by T across d; coalesced across lanes) + normalize.
    const float* xp = in + (size_t)b * DD * TT + t;
    float x[DD];
    float ss = 0.0f;
    #pragma unroll
    for (int d = 0; d < DD; ++d) { float v = xp[(size_t)d * TT]; x[d] = v; ss += v * v; }
    float inv = 1.0f / fmaxf(sqrtf(ss), 1e-12f);
    #pragma unroll
    for (int d = 0; d < DD; ++d) x[d] *= inv;

    float best = -3.402823466e+38f;
    int   bidx = 0;

    for (int kb = 0; kb < KK; kb += CHUNK_K) {
        __syncthreads();
        // Stage CHUNK_K codewords (float4 copies, fully coalesced).
        {
            const float4* src = (const float4*)(g_wnorm + kb * DD);
            float4*       dst = (float4*)sw;
            #pragma unroll
            for (int i = 0; i < (CHUNK_K * DD / 4) / BLOCK_T; ++i)
                dst[threadIdx.x + i * BLOCK_T] = src[threadIdx.x + i * BLOCK_T];
        }
        __syncthreads();

        for (int kk = 0; kk < CHUNK_K; ++kk) {
            const float4* w4 = (const float4*)(sw + kk * DD);
            float dot = 0.0f;
            #pragma unroll
            for (int j = 0; j < DD / 4; ++j) {
                float4 w = w4[j];
                dot += x[4 * j + 0] * w.x;
                dot += x[4 * j + 1] * w.y;
                dot += x[4 * j + 2] * w.z;
                dot += x[4 * j + 3] * w.w;
            }
            // argmin(2-2*dot) == argmax(dot); strict '>' keeps first index on ties
            if (dot > best) { best = dot; bidx = kb + kk; }
        }
    }

    // Gather chosen codeword, write quantized (transposed layout), accumulate error.
    const float* wn = g_wnorm + bidx * DD;
    float* qp = out + 1 + (size_t)b * DD * TT + t;
    float err = 0.0f;
    #pragma unroll
    for (int d = 0; d < DD; ++d) {
        float q = wn[d];
        qp[(size_t)d * TT] = q;
        float e = q - x[d];
        err += e * e;
    }
    out[1 + QELEMS + n] = (float)bidx;

    // Deterministic block tree-reduce of squared error.
    red[threadIdx.x] = err;
    __syncthreads();
    #pragma unroll
    for (int s = BLOCK_T / 2; s > 0; s >>= 1) {
        if (threadIdx.x < s) red[threadIdx.x] += red[threadIdx.x + s];
        __syncthreads();
    }
    if (threadIdx.x == 0) g_partial[blockIdx.x] = red[0];
}

// ---------------------------------------------------------------------------
// Kernel C: deterministic final reduce -> loss; also writes n_resurrected = 0.
// loss = (1 + 0.25) * mean((q - x_norm)^2)  since e_latent == q_latent in value.
// ---------------------------------------------------------------------------
__global__ void finalize_kernel(float* __restrict__ out, int out_size) {
    __shared__ float red[GRID_B];
    red[threadIdx.x] = g_partial[threadIdx.x];
    __syncthreads();
    #pragma unroll
    for (int s = GRID_B / 2; s > 0; s >>= 1) {
        if (threadIdx.x < s) red[threadIdx.x] += red[threadIdx.x + s];
        __syncthreads();
    }
    if (threadIdx.x == 0) {
        out[0] = 1.25f * red[0] / (float)QELEMS;
        out[out_size - 1] = 0.0f;   // n_resurrected
    }
}

// ---------------------------------------------------------------------------
extern "C" void kernel_launch(void* const* d_in, const int* in_sizes, int n_in,
                              void* d_out, int out_size) {
    const float* in = (const float*)d_in[0];   // [B, D, T] float32
    const float* w  = (const float*)d_in[1];   // [K, D]    float32
    float* out = (float*)d_out;

    norm_weight_kernel<<<KK / 8, dim3(32, 8)>>>(w);
    vq_main_kernel<<<GRID_B, BLOCK_T>>>(in, out);
    finalize_kernel<<<1, GRID_B>>>(out, out_size);
}